// round 15
// baseline (speedup 1.0000x reference)
#include <cuda_runtime.h>

#define HH 128
#define WW 128
#define CC 16
#define FF 16
#define CF (CC * FF)
#define NB 2
#define SNX 32
#define SNY 32
#define NG 33            // aligned 4x4 groups / x-blocks / y-blocks: 0..32

// Group sums: G = sum b over 4x4 group, P = sum pet*b. 1.1 MB each.
__device__ float g_G[(size_t)NB * NG * NG * CF];
__device__ float g_P[(size_t)NB * NG * NG * CF];
// Ssum[bz][a][blk][cf]: per (x-block, y-block) sum of covering-window ratios. 2.2 MB.
__device__ float g_S[(size_t)NB * NG * NG * CF];

// 32-byte evict_last load (only legal width for the hint on this ptxas).
__device__ __forceinline__ void ldg_el32B(const float* p, float4& a, float4& b) {
    unsigned long long r0, r1, r2, r3;
    asm volatile("ld.global.nc.L2::evict_last.v4.b64 {%0,%1,%2,%3}, [%4];"
                 : "=l"(r0), "=l"(r1), "=l"(r2), "=l"(r3) : "l"(p));
    a.x = __uint_as_float((unsigned)r0); a.y = __uint_as_float((unsigned)(r0 >> 32));
    a.z = __uint_as_float((unsigned)r1); a.w = __uint_as_float((unsigned)(r1 >> 32));
    b.x = __uint_as_float((unsigned)r2); b.y = __uint_as_float((unsigned)(r2 >> 32));
    b.z = __uint_as_float((unsigned)r3); b.w = __uint_as_float((unsigned)(r3 >> 32));
}

// ---------------------------------------------------------------------------
// K1: group sums, double-buffered prefetch over groups (proven ~4.4us).
// ---------------------------------------------------------------------------
__global__ __launch_bounds__(256) void groupsum_kernel(
    const float* __restrict__ pet, const float* __restrict__ bfeat)
{
    __shared__ float pet_s[4 * 36 * CC];   // 9.2 KB

    const int q  = blockIdx.x;             // 0..3
    const int gx = blockIdx.y;             // 0..32
    const int bz = blockIdx.z;
    const int t  = threadIdx.x;
    const int c  = t >> 4;

    const int ngy   = (q == 3) ? 9 : 8;
    const int gy0   = q * 8;
    const int c0    = 4 * gy0 - 2;
    const int ncols = 4 * ngy;
    const int r0    = 4 * gx - 2;

    for (int idx = t; idx < 4 * ncols * CC; idx += 256) {
        int cc = idx & 15, pix = idx >> 4;
        int u = pix / ncols, v = pix - u * ncols;
        int r = r0 + u, col = c0 + v;
        float val = 0.f;
        if ((unsigned)r < HH && (unsigned)col < WW)
            val = pet[((bz * HH + r) * WW + col) * CC + cc];
        pet_s[idx] = val;
    }
    __syncthreads();

    const float* bb = bfeat + (size_t)bz * HH * WW * CF + t;

    float buf[2][16];
    auto load_group = [&](int g, float* dst) {
#pragma unroll
        for (int u = 0; u < 4; u++) {
            int r = r0 + u;
            bool rowok = (unsigned)r < HH;
#pragma unroll
            for (int v = 0; v < 4; v++) {
                int col = c0 + 4 * g + v;
                float x = 0.f;
                if (rowok && (unsigned)col < WW)
                    x = __ldg(bb + (r * WW + col) * CF);
                dst[u * 4 + v] = x;
            }
        }
    };

    load_group(0, buf[0]);
#pragma unroll
    for (int g = 0; g < 9; g++) {
        if (g >= ngy) continue;
        if (g + 1 < ngy) load_group(g + 1, buf[(g + 1) & 1]);
        const float* B = buf[g & 1];
        float d = 0.f, p = 0.f;
#pragma unroll
        for (int u = 0; u < 4; u++)
#pragma unroll
            for (int v = 0; v < 4; v++) {
                float bv = B[u * 4 + v];
                float pv = pet_s[(u * ncols + 4 * g + v) * CC + c];
                d += bv;
                p = fmaf(pv, bv, p);
            }
        size_t o = (((size_t)bz * NG + gx) * NG + (gy0 + g)) * CF + t;
        g_G[o] = d;
        g_P[o] = p;
    }
}

// ---------------------------------------------------------------------------
// K2: Ssum[a][blk] = sum over valid windows snx in {a-1,a}, sny in {blk-1,blk}
// of divide_no_nan(P2, G2). Streams G/P rows with running x-pair sums.
// G/P are L2-hot from K1.
// ---------------------------------------------------------------------------
__global__ __launch_bounds__(256) void ratiosum_kernel()
{
    const int qy = blockIdx.x;   // 0..3 (blk quarter)
    const int a  = blockIdx.y;   // 0..32
    const int bz = blockIdx.z;
    const int t  = threadIdx.x;

    const int nblk = (qy == 3) ? 9 : 8;
    const int blk0 = 8 * qy;

    const bool snx0ok = (a >= 1);        // snx = a-1
    const bool snx1ok = (a <= 31);       // snx = a

    float S[9];
#pragma unroll
    for (int s = 0; s < 9; s++) S[s] = 0.f;

    float xg0p = 0.f, xg1p = 0.f, xp0p = 0.f, xp1p = 0.f;
#pragma unroll
    for (int w = 0; w <= 10; w++) {
        if (w > nblk + 1) continue;
        int gy = blk0 - 1 + w;
        float g0 = 0.f, g1 = 0.f, g2v = 0.f;
        float p0 = 0.f, p1 = 0.f, p2v = 0.f;
        if ((unsigned)gy < NG) {
#pragma unroll
            for (int ii = 0; ii < 3; ii++) {
                int gxx = a - 1 + ii;
                if ((unsigned)gxx >= NG) continue;
                size_t o = (((size_t)bz * NG + gxx) * NG + gy) * CF + t;
                float gv = __ldg(&g_G[o]);
                float pv = __ldg(&g_P[o]);
                if (ii == 0)      { g0 = gv; p0 = pv; }
                else if (ii == 1) { g1 = gv; p1 = pv; }
                else              { g2v = gv; p2v = pv; }
            }
        }
        float xg0 = g0 + g1, xg1 = g1 + g2v;
        float xp0 = p0 + p1, xp1 = p1 + p2v;
        if (w >= 1) {
            int sny = blk0 + w - 2;
            float rsum = 0.f;
            if ((unsigned)sny < SNY) {
                float G20 = xg0p + xg0, P20 = xp0p + xp0;
                float G21 = xg1p + xg1, P21 = xp1p + xp1;
                if (snx0ok && G20 != 0.f) rsum += P20 / G20;
                if (snx1ok && G21 != 0.f) rsum += P21 / G21;
            }
            int sidx = sny - blk0;          // covers blks sidx, sidx+1
            if (sidx >= 0)          S[sidx] += rsum;
            if (sidx + 1 <= nblk-1) S[sidx + 1] += rsum;
        }
        xg0p = xg0; xg1p = xg1; xp0p = xp0; xp1p = xp1;
    }

#pragma unroll
    for (int s = 0; s < 9; s++) {
        if (s >= nblk) continue;
        g_S[(((size_t)bz * NG + a) * NG + (blk0 + s)) * CF + t] = S[s];
    }
}

// ---------------------------------------------------------------------------
// K3: out(x,y,c) = 0.25 * sum_f b[x,y,c,f] * Ssum[a][blk][c,f].
// Pure stream: 4 b loads + 2 S loads per thread, no smem, no syncthreads.
// ---------------------------------------------------------------------------
__global__ __launch_bounds__(256) void apply_kernel(
    const float* __restrict__ bfeat, float* __restrict__ out)
{
    const int A2 = blockIdx.x;   // 0..16 (y-block pair)
    const int a  = blockIdx.y;   // 0..32 (x-block)
    const int bz = blockIdx.z;
    const int t  = threadIdx.x;

    const int q5 = t & 31;       // 32B slot within pixel record
    const int pp = t >> 5;
    const int i  = pp & 3;       // x-row
    const int yh = pp >> 2;      // which y-block of the pair
    const int c  = q5 >> 1;
    const int fh = q5 & 1;

    const int x   = 4 * a - 2 + i;
    const int blk = 2 * A2 + yh;            // 0..33 (33 -> fully out of range)
    const bool okx   = (unsigned)x < HH;
    const bool okblk = blk < NG;

    const float* rowbase = bfeat + ((size_t)(bz * HH + x) * WW) * CF + q5 * 8;

    // ---- 4 independent 32B b loads ----
    float4 bva[4], bvb[4];
#pragma unroll
    for (int m = 0; m < 4; m++) {
        int y = 4 * blk - 2 + m;
        if (okx && (unsigned)y < WW) {
            ldg_el32B(rowbase + (size_t)y * CF, bva[m], bvb[m]);
        } else {
            bva[m] = make_float4(0.f, 0.f, 0.f, 0.f);
            bvb[m] = make_float4(0.f, 0.f, 0.f, 0.f);
        }
    }

    // ---- 2 independent 16B S loads (contiguous cf slice) ----
    float4 sv0 = make_float4(0.f, 0.f, 0.f, 0.f);
    float4 sv1 = sv0;
    if (okblk) {
        const float* sp = g_S + (((size_t)bz * NG + a) * NG + blk) * CF + q5 * 8;
        sv0 = __ldg((const float4*)sp);
        sv1 = __ldg((const float4*)(sp + 4));
    }

    const bool lead = (fh == 0);
#pragma unroll
    for (int m = 0; m < 4; m++) {
        int y = 4 * blk - 2 + m;
        float dot = bva[m].x * sv0.x + bva[m].y * sv0.y
                  + bva[m].z * sv0.z + bva[m].w * sv0.w
                  + bvb[m].x * sv1.x + bvb[m].y * sv1.y
                  + bvb[m].z * sv1.z + bvb[m].w * sv1.w;
        dot += __shfl_xor_sync(0xffffffffu, dot, 1);
        if (lead && okx && (unsigned)y < WW)
            out[((bz * HH + x) * WW + y) * CC + c] = 0.25f * dot;
    }
}

extern "C" void kernel_launch(void* const* d_in, const int* in_sizes, int n_in,
                              void* d_out, int out_size)
{
    // Input order per reference signature: mr (unused), pet, b, px, py, sx, sy
    const float* pet   = (const float*)d_in[1];
    const float* bfeat = (const float*)d_in[2];

    dim3 grid1(4, NG, NB);                   // 264 CTAs
    groupsum_kernel<<<grid1, 256>>>(pet, bfeat);

    dim3 grid2(4, NG, NB);                   // 264 CTAs
    ratiosum_kernel<<<grid2, 256>>>();

    dim3 grid3(17, NG, NB);                  // 1122 CTAs
    apply_kernel<<<grid3, 256>>>(bfeat, (float*)d_out);
}

// round 16
// speedup vs baseline: 1.3617x; 1.3617x over previous
#include <cuda_runtime.h>

#define HH 128
#define WW 128
#define CC 16
#define FF 16
#define CF (CC * FF)
#define NB 2
#define SNX 32
#define SNY 32
#define NG 33            // aligned 4x4 groups: start = 4g-2, g = 0..32

// Group sums: G = sum b over 4x4 group, P = sum pet*b. 1.1 MB each.
__device__ float g_G[(size_t)NB * NG * NG * CF];
__device__ float g_P[(size_t)NB * NG * NG * CF];

// 32-byte evict_last load (only legal width for the hint on this ptxas).
__device__ __forceinline__ void ldg_el32B(const float* p, float4& a, float4& b) {
    unsigned long long r0, r1, r2, r3;
    asm volatile("ld.global.nc.L2::evict_last.v4.b64 {%0,%1,%2,%3}, [%4];"
                 : "=l"(r0), "=l"(r1), "=l"(r2), "=l"(r3) : "l"(p));
    a.x = __uint_as_float((unsigned)r0); a.y = __uint_as_float((unsigned)(r0 >> 32));
    a.z = __uint_as_float((unsigned)r1); a.w = __uint_as_float((unsigned)(r1 >> 32));
    b.x = __uint_as_float((unsigned)r2); b.y = __uint_as_float((unsigned)(r2 >> 32));
    b.z = __uint_as_float((unsigned)r3); b.w = __uint_as_float((unsigned)(r3 >> 32));
}

// ---------------------------------------------------------------------------
// K1: group sums, WIDE grid (1122 CTAs). CTA = (gy-pair qp, gx, bz).
// Each thread issues all 32 b loads up-front, then accumulates.
// ---------------------------------------------------------------------------
template<int NGY>
__device__ __forceinline__ void groupsum_impl(
    int qp, int gx, int bz, int t,
    const float* __restrict__ pet, const float* __restrict__ bfeat,
    float* pet_s)
{
    const int c     = t >> 4;
    const int gy0   = 2 * qp;
    const int c0    = 4 * gy0 - 2;
    const int ncols = 4 * NGY;
    const int r0    = 4 * gx - 2;

    // stage pet for the 4 x ncols strip (zero outside image)
    for (int idx = t; idx < 4 * ncols * CC; idx += 256) {
        int cc = idx & 15, pix = idx >> 4;
        int u = pix / ncols, v = pix - u * ncols;
        int r = r0 + u, col = c0 + v;
        float val = 0.f;
        if ((unsigned)r < HH && (unsigned)col < WW)
            val = pet[((bz * HH + r) * WW + col) * CC + cc];
        pet_s[idx] = val;
    }
    __syncthreads();

    const float* bb = bfeat + (size_t)bz * HH * WW * CF + t;

    // issue ALL b loads first (max MLP), then accumulate
    float bv[4 * 4 * NGY];
#pragma unroll
    for (int u = 0; u < 4; u++) {
        int r = r0 + u;
        bool rowok = (unsigned)r < HH;
#pragma unroll
        for (int v = 0; v < ncols; v++) {
            int col = c0 + v;
            float x = 0.f;
            if (rowok && (unsigned)col < WW)
                x = __ldg(bb + (r * WW + col) * CF);
            bv[u * ncols + v] = x;
        }
    }

    float d[NGY], p[NGY];
#pragma unroll
    for (int g = 0; g < NGY; g++) { d[g] = 0.f; p[g] = 0.f; }
#pragma unroll
    for (int u = 0; u < 4; u++)
#pragma unroll
        for (int v = 0; v < ncols; v++) {
            const int g = v >> 2;
            float b = bv[u * ncols + v];
            float pv = pet_s[(u * ncols + v) * CC + c];
            d[g] += b;
            p[g] = fmaf(pv, b, p[g]);
        }

#pragma unroll
    for (int g = 0; g < NGY; g++) {
        size_t o = (((size_t)bz * NG + gx) * NG + (gy0 + g)) * CF + t;
        g_G[o] = d[g];
        g_P[o] = p[g];
    }
}

__global__ __launch_bounds__(256) void groupsum_kernel(
    const float* __restrict__ pet, const float* __restrict__ bfeat)
{
    __shared__ float pet_s[4 * 8 * CC];    // 2 KB
    const int qp = blockIdx.x;             // 0..16
    const int gx = blockIdx.y;             // 0..32
    const int bz = blockIdx.z;
    const int t  = threadIdx.x;
    if (qp < 16) groupsum_impl<2>(qp, gx, bz, t, pet, bfeat, pet_s);
    else         groupsum_impl<1>(qp, gx, bz, t, pet, bfeat, pet_s);
}

// ---------------------------------------------------------------------------
// K2: apply (R13 version verbatim — best measured).
// 32 threads/pixel, 32B evict_last loads, 4 y-pixels per thread, inline S.
// ---------------------------------------------------------------------------
template<bool FULL>
__device__ __forceinline__ void apply_impl(
    int A2, int a, int bz, int t,
    const float* __restrict__ bfeat, float* __restrict__ out)
{
    __shared__ float S2[2][CF];   // natural layout, index = cf

    const int q5 = t & 31;        // 32B slot within pixel record
    const int pp = t >> 5;
    const int i  = pp & 3;        // x-row
    const int yh = pp >> 2;       // which y-block of the pair (0/1)
    const int c  = q5 >> 1;
    const int fh = q5 & 1;

    const int x = 4 * a - 2 + i;
    const bool okx = FULL || ((unsigned)x < HH);
    const float* rowbase = bfeat + ((size_t)(bz * HH + x) * WW) * CF + q5 * 8;
    const int y0 = 8 * A2 - 2 + 4 * yh;

    // ---- issue 4 independent 32B b loads first ----
    float4 bva[4], bvb[4];
#pragma unroll
    for (int m = 0; m < 4; m++) {
        int y = y0 + m;
        if (FULL || (okx && (unsigned)y < WW)) {
            ldg_el32B(rowbase + (size_t)y * CF, bva[m], bvb[m]);
        } else {
            bva[m] = make_float4(0.f, 0.f, 0.f, 0.f);
            bvb[m] = make_float4(0.f, 0.f, 0.f, 0.f);
        }
    }

    // ---- load G/P neighborhood folded into x-pair sums (t = cf index) ----
    float xg[2][4], xp[2][4];
#pragma unroll
    for (int j = 0; j < 4; j++) {
        int gy = 2 * A2 - 1 + j;
        float g0 = 0.f, g1 = 0.f, g2v = 0.f;
        float p0 = 0.f, p1 = 0.f, p2v = 0.f;
        if (FULL || (unsigned)gy < NG) {
#pragma unroll
            for (int ii = 0; ii < 3; ii++) {
                int gxx = a - 1 + ii;
                if (!FULL && (unsigned)gxx >= NG) continue;
                size_t o = (((size_t)bz * NG + gxx) * NG + gy) * CF + t;
                float gv = __ldg(&g_G[o]);
                float pv = __ldg(&g_P[o]);
                if (ii == 0)      { g0 = gv; p0 = pv; }
                else if (ii == 1) { g1 = gv; p1 = pv; }
                else              { g2v = gv; p2v = pv; }
            }
        }
        xg[0][j] = g0 + g1;  xg[1][j] = g1 + g2v;
        xp[0][j] = p0 + p1;  xp[1][j] = p1 + p2v;
    }

    // ---- S for the two y-blocks ----
#pragma unroll
    for (int s = 0; s < 2; s++) {
        int blk = 2 * A2 + s;
        float acc = 0.f;
#pragma unroll
        for (int da = 0; da < 2; da++) {
            int snx = a - 1 + da;
            if (!FULL && (unsigned)snx >= SNX) continue;
#pragma unroll
            for (int db = 0; db < 2; db++) {
                int sny = blk - 1 + db;
                if (!FULL && (unsigned)sny >= SNY) continue;
                int j0 = s + db;
                float g2 = xg[da][j0] + xg[da][j0 + 1];
                float p2 = xp[da][j0] + xp[da][j0 + 1];
                acc += (g2 != 0.f) ? (p2 / g2) : 0.f;   // divide_no_nan
            }
        }
        S2[s][t] = acc;
    }
    __syncthreads();

    const float4 sv0 = *(const float4*)(&S2[yh][q5 * 8]);
    const float4 sv1 = *(const float4*)(&S2[yh][q5 * 8 + 4]);

    const bool lead = (fh == 0);
#pragma unroll
    for (int m = 0; m < 4; m++) {
        int y = y0 + m;
        float dot = bva[m].x * sv0.x + bva[m].y * sv0.y
                  + bva[m].z * sv0.z + bva[m].w * sv0.w
                  + bvb[m].x * sv1.x + bvb[m].y * sv1.y
                  + bvb[m].z * sv1.z + bvb[m].w * sv1.w;
        dot += __shfl_xor_sync(0xffffffffu, dot, 1);
        if (lead && (FULL || (okx && (unsigned)y < WW)))
            out[((bz * HH + x) * WW + y) * CC + c] = 0.25f * dot;
    }
}

__global__ __launch_bounds__(256) void apply_kernel(
    const float* __restrict__ bfeat, float* __restrict__ out)
{
    const int A2 = blockIdx.x;   // 0..16
    const int a  = blockIdx.y;   // 0..32
    const int bz = blockIdx.z;
    const int t  = threadIdx.x;

    const bool interior = (a >= 1) && (a <= 31) && (A2 >= 1) && (A2 <= 15);
    if (interior) apply_impl<true >(A2, a, bz, t, bfeat, out);
    else          apply_impl<false>(A2, a, bz, t, bfeat, out);
}

extern "C" void kernel_launch(void* const* d_in, const int* in_sizes, int n_in,
                              void* d_out, int out_size)
{
    // Input order per reference signature: mr (unused), pet, b, px, py, sx, sy
    const float* pet   = (const float*)d_in[1];
    const float* bfeat = (const float*)d_in[2];

    dim3 grid1(17, NG, NB);                  // 1122 CTAs
    groupsum_kernel<<<grid1, 256>>>(pet, bfeat);

    dim3 grid2(17, NG, NB);                  // 1122 CTAs
    apply_kernel<<<grid2, 256>>>(bfeat, (float*)d_out);
}